// round 15
// baseline (speedup 1.0000x reference)
#include <cuda_runtime.h>
#include <math.h>
#include <stdint.h>

#define BATCH 4
#define C 64
#define HH 256
#define WW 256
#define NPIX (HH*WW)
#define NHEADS 8
#define NTILE 64              // row tiles (4 rows each)
#define PITCHU 136            // uint32 smem pitch in gemm kernels
#define PAD 1028              // smem floats per channel row-block (16B-aligned)

// ---------------- scratch (static device globals) ----------------
__device__ uint16_t g_midQ16[BATCH*C*NPIX];   // bf16 conv1x1(q) output
__device__ uint16_t g_midK16[BATCH*C*NPIX];   // bf16 conv1x1(k) output
__device__ float    g_midV[BATCH*C*NPIX];     // fp32 (precision-critical path)
__device__ float    g_V[BATCH*C*NPIX];
__device__ float    g_part[BATCH*NHEADS*NTILE*80];
__device__ float    g_weff[BATCH*C*C];

// ---------------- bf16 helpers ----------------
__device__ __forceinline__ uint32_t rbf16(float x){
    uint32_t b = __float_as_uint(x);
    return (b + 0x7FFFu + ((b >> 16) & 1u)) >> 16;
}
__device__ __forceinline__ void split2(float x0, float x1, uint32_t& hi, uint32_t& lo){
    const uint32_t h0 = rbf16(x0), h1 = rbf16(x1);
    hi = h0 | (h1 << 16);
    const float r0 = x0 - __uint_as_float(h0 << 16);
    const float r1 = x1 - __uint_as_float(h1 << 16);
    asm("cvt.rn.bf16x2.f32 %0, %1, %2;" : "=r"(lo) : "f"(r1), "f"(r0));
}
__device__ __forceinline__ uint32_t packbf2(float lo, float hi){
    uint32_t p;
    asm("cvt.rn.bf16x2.f32 %0, %1, %2;" : "=r"(p) : "f"(hi), "f"(lo));
    return p;
}
__device__ __forceinline__ float bf2f(uint32_t v){ return __uint_as_float(v << 16); }

#define MMA_BF16(c0,c1,c2,c3,a0,a1,a2,a3,b0,b1) \
  asm volatile("mma.sync.aligned.m16n8k16.row.col.f32.bf16.bf16.f32 " \
    "{%0,%1,%2,%3}, {%4,%5,%6,%7}, {%8,%9}, {%0,%1,%2,%3};" \
    : "+f"(c0),"+f"(c1),"+f"(c2),"+f"(c3) \
    : "r"(a0),"r"(a1),"r"(a2),"r"(a3),"r"(b0),"r"(b1))

// ============ gemm_bf16: 64 out ch; OB16 selects bf16 vs fp32 output ==========
template<bool OB16>
__global__ void __launch_bounds__(128) gemm_bf16(
    const float* __restrict__ in, const float* __restrict__ w,
    void* __restrict__ out, int w_per_batch)
{
    __shared__ uint32_t s_hi[32*PITCHU];
    __shared__ uint32_t s_lo[32*PITCHU];

    const int tid  = threadIdx.x;
    const int lane = tid & 31, warp = tid >> 5;
    const int b    = blockIdx.y;
    const int px0  = blockIdx.x * 128;
    const int gid  = lane >> 2, tig = lane & 3;

    const float* wb = w + (w_per_batch ? b*C*C : 0);
    uint32_t Wh[4][4], Wl[4][4];
    #pragma unroll
    for (int kc = 0; kc < 4; kc++) {
        #pragma unroll
        for (int j = 0; j < 4; j++) {
            const int row = warp*16 + gid + (j & 1)*8;
            const int p   = 8*kc + tig + (j >> 1)*4;
            const float2 x = *(const float2*)(wb + row*C + 2*p);
            split2(x.x, x.y, Wh[kc][j], Wl[kc][j]);
        }
    }

    const float* ib = in + (size_t)b*(C*NPIX) + px0;
    #pragma unroll
    for (int i = 0; i < 8; i++) {
        const int p = warp + 4*i;
        const float4 e = *(const float4*)(ib + (size_t)(2*p  )*NPIX + lane*4);
        const float4 o = *(const float4*)(ib + (size_t)(2*p+1)*NPIX + lane*4);
        uint32_t h0,l0,h1,l1,h2,l2,h3,l3;
        split2(e.x, o.x, h0, l0); split2(e.y, o.y, h1, l1);
        split2(e.z, o.z, h2, l2); split2(e.w, o.w, h3, l3);
        *(uint4*)(s_hi + p*PITCHU + lane*4) = make_uint4(h0,h1,h2,h3);
        *(uint4*)(s_lo + p*PITCHU + lane*4) = make_uint4(l0,l1,l2,l3);
    }
    __syncthreads();

    const int co_base = warp*16;
    #pragma unroll 2
    for (int nt = 0; nt < 16; nt++) {
        float A0=0.f,A1=0.f,A2=0.f,A3=0.f;
        float B0=0.f,B1=0.f,B2=0.f,B3=0.f;
        float D0=0.f,D1=0.f,D2=0.f,D3=0.f;
        const int pxl = nt*8 + gid;
        #pragma unroll
        for (int kc = 0; kc < 4; kc++) {
            const int r0 = (8*kc + tig)*PITCHU + pxl;
            const int r1 = r0 + 4*PITCHU;
            const uint32_t b0h = s_hi[r0], b1h = s_hi[r1];
            const uint32_t b0l = s_lo[r0], b1l = s_lo[r1];
            MMA_BF16(A0,A1,A2,A3, Wh[kc][0],Wh[kc][1],Wh[kc][2],Wh[kc][3], b0h,b1h);
            MMA_BF16(B0,B1,B2,B3, Wh[kc][0],Wh[kc][1],Wh[kc][2],Wh[kc][3], b0l,b1l);
            MMA_BF16(D0,D1,D2,D3, Wl[kc][0],Wl[kc][1],Wl[kc][2],Wl[kc][3], b0h,b1h);
        }
        const float c0 = A0 + B0 + D0, c1 = A1 + B1 + D1;
        const float c2 = A2 + B2 + D2, c3 = A3 + B3 + D3;
        const int pxs = nt*8 + tig*2;
        if (OB16) {
            uint16_t* ob = (uint16_t*)out + (size_t)b*(C*NPIX) + px0;
            *(uint32_t*)(ob + (size_t)(co_base+gid  )*NPIX + pxs) = packbf2(c0, c1);
            *(uint32_t*)(ob + (size_t)(co_base+gid+8)*NPIX + pxs) = packbf2(c2, c3);
        } else {
            float* ob = (float*)out + (size_t)b*(C*NPIX) + px0;
            *(float2*)(ob + (size_t)(co_base+gid  )*NPIX + pxs) = make_float2(c0, c1);
            *(float2*)(ob + (size_t)(co_base+gid+8)*NPIX + pxs) = make_float2(c2, c3);
        }
    }
}

// ======== gemm_bf16_kv: K (bf16 out) + V (fp32 out), input staged once ========
__global__ void __launch_bounds__(256) gemm_bf16_kv(
    const float* __restrict__ in, const float* __restrict__ w,
    uint16_t* __restrict__ outK, float* __restrict__ outV)
{
    __shared__ uint32_t s_hi[32*PITCHU];
    __shared__ uint32_t s_lo[32*PITCHU];

    const int tid  = threadIdx.x;
    const int lane = tid & 31, warp = tid >> 5;
    const int b    = blockIdx.y;
    const int px0  = blockIdx.x * 128;
    const int gid  = lane >> 2, tig = lane & 3;

    uint32_t Wh[4][4], Wl[4][4];
    #pragma unroll
    for (int kc = 0; kc < 4; kc++) {
        #pragma unroll
        for (int j = 0; j < 4; j++) {
            const int row = warp*16 + gid + (j & 1)*8;
            const int p   = 8*kc + tig + (j >> 1)*4;
            const float2 x = *(const float2*)(w + row*C + 2*p);
            split2(x.x, x.y, Wh[kc][j], Wl[kc][j]);
        }
    }

    const float* ib = in + (size_t)b*(C*NPIX) + px0;
    #pragma unroll
    for (int i = 0; i < 4; i++) {
        const int p = warp + 8*i;
        const float4 e = *(const float4*)(ib + (size_t)(2*p  )*NPIX + lane*4);
        const float4 o = *(const float4*)(ib + (size_t)(2*p+1)*NPIX + lane*4);
        uint32_t h0,l0,h1,l1,h2,l2,h3,l3;
        split2(e.x, o.x, h0, l0); split2(e.y, o.y, h1, l1);
        split2(e.z, o.z, h2, l2); split2(e.w, o.w, h3, l3);
        *(uint4*)(s_hi + p*PITCHU + lane*4) = make_uint4(h0,h1,h2,h3);
        *(uint4*)(s_lo + p*PITCHU + lane*4) = make_uint4(l0,l1,l2,l3);
    }
    __syncthreads();

    const int co_base = warp*16;
    const int co_loc = co_base & 63;
    const bool isK = (co_base < 64);
    #pragma unroll 2
    for (int nt = 0; nt < 16; nt++) {
        float A0=0.f,A1=0.f,A2=0.f,A3=0.f;
        float B0=0.f,B1=0.f,B2=0.f,B3=0.f;
        const int pxl = nt*8 + gid;
        #pragma unroll
        for (int kc = 0; kc < 4; kc++) {
            const int r0 = (8*kc + tig)*PITCHU + pxl;
            const int r1 = r0 + 4*PITCHU;
            const uint32_t b0h = s_hi[r0], b1h = s_hi[r1];
            const uint32_t b0l = s_lo[r0], b1l = s_lo[r1];
            MMA_BF16(A0,A1,A2,A3, Wh[kc][0],Wh[kc][1],Wh[kc][2],Wh[kc][3], b0h,b1h);
            MMA_BF16(B0,B1,B2,B3, Wh[kc][0],Wh[kc][1],Wh[kc][2],Wh[kc][3], b0l,b1l);
            MMA_BF16(B0,B1,B2,B3, Wl[kc][0],Wl[kc][1],Wl[kc][2],Wl[kc][3], b0h,b1h);
        }
        const float c0 = A0 + B0, c1 = A1 + B1, c2 = A2 + B2, c3 = A3 + B3;
        const int pxs = nt*8 + tig*2;
        if (isK) {
            uint16_t* ob = outK + (size_t)b*(C*NPIX) + px0;
            *(uint32_t*)(ob + (size_t)(co_loc+gid  )*NPIX + pxs) = packbf2(c0, c1);
            *(uint32_t*)(ob + (size_t)(co_loc+gid+8)*NPIX + pxs) = packbf2(c2, c3);
        } else {
            float* ob = outV + (size_t)b*(C*NPIX) + px0;
            *(float2*)(ob + (size_t)(co_loc+gid  )*NPIX + pxs) = make_float2(c0, c1);
            *(float2*)(ob + (size_t)(co_loc+gid+8)*NPIX + pxs) = make_float2(c2, c3);
        }
    }
}

// ---------------- sliding-window row fetch (bf16 source) ----------------------
__device__ __forceinline__ void fetch_row16(
    const uint16_t* __restrict__ ic, int yy, int x4, float4& m, float& l, float& r)
{
    if (yy < 0 || yy >= HH) { m = make_float4(0.f,0.f,0.f,0.f); l = 0.f; r = 0.f; return; }
    const uint16_t* row = ic + yy*WW;
    const uint2 a = *(const uint2*)(row + x4);       // 4 bf16, 8B-aligned
    m.x = __uint_as_float(a.x << 16);
    m.y = __uint_as_float(a.x & 0xffff0000u);
    m.z = __uint_as_float(a.y << 16);
    m.w = __uint_as_float(a.y & 0xffff0000u);
    l = (x4 > 0)      ? bf2f(__ldg(row + x4 - 1)) : 0.f;
    r = (x4 + 4 < WW) ? bf2f(__ldg(row + x4 + 4)) : 0.f;
}
// fp32 source (V path)
__device__ __forceinline__ void fetch_row(
    const float* __restrict__ ic, int yy, int x4, float4& m, float& l, float& r)
{
    if (yy < 0 || yy >= HH) { m = make_float4(0.f,0.f,0.f,0.f); l = 0.f; r = 0.f; return; }
    const float* row = ic + yy*WW;
    m = *(const float4*)(row + x4);
    l = (x4 > 0)      ? __ldg(row + x4 - 1) : 0.f;
    r = (x4 + 4 < WW) ? __ldg(row + x4 + 4) : 0.f;
}
__device__ __forceinline__ float4 stencil3(
    const float4& m0, float l0, float r0, const float4& m1, float l1, float r1,
    const float4& m2, float l2, float r2, const float* wr)
{
    float a0, a1, a2, a3;
    a0  = wr[0]*l0   + wr[1]*m0.x + wr[2]*m0.y;
    a1  = wr[0]*m0.x + wr[1]*m0.y + wr[2]*m0.z;
    a2  = wr[0]*m0.y + wr[1]*m0.z + wr[2]*m0.w;
    a3  = wr[0]*m0.z + wr[1]*m0.w + wr[2]*r0;
    a0 += wr[3]*l1   + wr[4]*m1.x + wr[5]*m1.y;
    a1 += wr[3]*m1.x + wr[4]*m1.y + wr[5]*m1.z;
    a2 += wr[3]*m1.y + wr[4]*m1.z + wr[5]*m1.w;
    a3 += wr[3]*m1.z + wr[4]*m1.w + wr[5]*r1;
    a0 += wr[6]*l2   + wr[7]*m2.x + wr[8]*m2.y;
    a1 += wr[6]*m2.x + wr[7]*m2.y + wr[8]*m2.z;
    a2 += wr[6]*m2.y + wr[7]*m2.z + wr[8]*m2.w;
    a3 += wr[6]*m2.z + wr[7]*m2.w + wr[8]*r2;
    return make_float4(a0, a1, a2, a3);
}
__device__ __forceinline__ float dot4(const float4& a, const float4& b){
    return a.x*b.x + a.y*b.y + a.z*b.z + a.w*b.w;
}

// ============ dwqk_attn: bf16 mid input, sliding-window phase 1 ===============
__global__ void __launch_bounds__(512, 2) dwqk_attn(
    const float* __restrict__ q_dw_w, const float* __restrict__ k_dw_w)
{
    __shared__ float s_q[8*PAD];
    __shared__ float s_k[8*PAD];
    __shared__ float s_red[80*16];

    const int tid  = threadIdx.x;
    const int tile = blockIdx.x;
    const int h    = blockIdx.y;
    const int b    = blockIdx.z;
    const int y0   = tile*4;

    const int lane = tid & 31, wrp = tid >> 5;

    // ---- phase 1: sliding-window depthwise on bf16 rows ----
    {
        const int grp = tid >> 8;              // 0: q, 1: k
        const int t   = tid & 255;
        const int cg  = t & 63, cp = t >> 6;   // x group, channel pair
        const int x4  = cg*4;

        const uint16_t* src = (grp ? g_midK16 : g_midQ16) + (size_t)b*(C*NPIX);
        const float* dwb = (grp ? k_dw_w : q_dw_w) + h*8*9;
        float* dst       = grp ? s_k : s_q;

        #pragma unroll
        for (int jj = 0; jj < 2; jj++) {
            const int j = cp*2 + jj;
            const uint16_t* ic = src + (size_t)(h*8 + j)*NPIX;
            float wr[9];
            #pragma unroll
            for (int i = 0; i < 9; i++) wr[i] = __ldg(dwb + j*9 + i);

            float4 m0, m1, m2; float l0, l1, l2, r0, r1, r2;
            fetch_row16(ic, y0 - 1, x4, m0, l0, r0);
            fetch_row16(ic, y0,     x4, m1, l1, r1);
            #pragma unroll
            for (int rowl = 0; rowl < 4; rowl++) {
                fetch_row16(ic, y0 + rowl + 1, x4, m2, l2, r2);
                const float4 res = stencil3(m0, l0, r0, m1, l1, r1, m2, l2, r2, wr);
                *(float4*)(dst + j*PAD + rowl*256 + x4) = res;
                m0 = m1; l0 = l1; r0 = r1;
                m1 = m2; l1 = l2; r1 = r2;
            }
        }
    }
    __syncthreads();

    // ---- phase 2: quad split, float4 pixel groups ----
    const int quad = tid & 3, slot = tid >> 2;
    float S[16], qs[2], ks[8];
    #pragma unroll
    for (int i = 0; i < 16; i++) S[i] = 0.f;
    qs[0] = qs[1] = 0.f;
    #pragma unroll
    for (int i = 0; i < 8; i++) ks[i] = 0.f;

    const float* qp = s_q + quad*2*PAD;
    #pragma unroll
    for (int it = 0; it < 2; it++) {
        const int n4 = it*512 + slot*4;
        const float4 q0 = *(const float4*)(qp + n4);
        const float4 q1 = *(const float4*)(qp + PAD + n4);
        qs[0] += dot4(q0, q0);
        qs[1] += dot4(q1, q1);
        #pragma unroll
        for (int jb = 0; jb < 2; jb++) {
            float4 kv[4];
            #pragma unroll
            for (int jj = 0; jj < 4; jj++)
                kv[jj] = *(const float4*)(s_k + (jb*4 + jj)*PAD + n4);
            #pragma unroll
            for (int jj = 0; jj < 4; jj++) {
                const int d = jb*4 + jj;
                S[d]     += dot4(q0, kv[jj]);
                S[8 + d] += dot4(q1, kv[jj]);
                ks[d]    += dot4(kv[jj], kv[jj]);
            }
        }
    }

    #pragma unroll
    for (int i = 0; i < 16; i++) {
        float v = S[i];
        #pragma unroll
        for (int o = 4; o <= 16; o <<= 1) v += __shfl_xor_sync(0xffffffffu, v, o);
        if (lane < 4) s_red[(i + 16*lane)*16 + wrp] = v;
    }
    #pragma unroll
    for (int i = 0; i < 2; i++) {
        float v = qs[i];
        #pragma unroll
        for (int o = 4; o <= 16; o <<= 1) v += __shfl_xor_sync(0xffffffffu, v, o);
        if (lane < 4) s_red[(64 + 2*lane + i)*16 + wrp] = v;
    }
    #pragma unroll
    for (int i = 0; i < 8; i++) {
        float v = ks[i];
        #pragma unroll
        for (int o = 1; o <= 16; o <<= 1) v += __shfl_xor_sync(0xffffffffu, v, o);
        if (lane == 0) s_red[(72 + i)*16 + wrp] = 0.25f*v;
    }
    __syncthreads();
    if (tid < 80) {
        float v = 0.f;
        #pragma unroll
        for (int w = 0; w < 16; w++) v += s_red[tid*16 + w];
        g_part[((b*NHEADS + h)*NTILE + tile)*80 + tid] = v;
    }
}

// ---------------- depthwise 3x3 (V path, fp32), sliding window ----------------
__global__ void __launch_bounds__(256) dw3x3(
    const float* __restrict__ in, const float* __restrict__ w,
    float* __restrict__ out)
{
    const int z = blockIdx.z;
    const float* ib = in + (size_t)z*NPIX;
    float* ob = out + (size_t)z*NPIX;
    const float* wc = w + (z & (C-1))*9;

    const int tid = threadIdx.x;
    const int x4  = (tid & 63)*4;
    const int y0  = blockIdx.y*16 + (tid >> 6)*4;

    float wr[9];
    #pragma unroll
    for (int i = 0; i < 9; i++) wr[i] = __ldg(wc + i);

    float4 m0, m1, m2; float l0, l1, l2, r0, r1, r2;
    fetch_row(ib, y0 - 1, x4, m0, l0, r0);
    fetch_row(ib, y0,     x4, m1, l1, r1);
    #pragma unroll
    for (int rowl = 0; rowl < 4; rowl++) {
        fetch_row(ib, y0 + rowl + 1, x4, m2, l2, r2);
        const float4 res = stencil3(m0, l0, r0, m1, l1, r1, m2, l2, r2, wr);
        *(float4*)(ob + (y0 + rowl)*WW + x4) = res;
        m0 = m1; l0 = l1; r0 = r1;
        m1 = m2; l1 = l2; r1 = r2;
    }
}

// ===== attn_tail: reduce partials + norms + softmax + weff in ONE launch ======
__global__ void __launch_bounds__(512) attn_tail(
    const float* __restrict__ temp, const float* __restrict__ proj_w)
{
    const int b = blockIdx.x;
    const int t = threadIdx.x;
    __shared__ float red[NHEADS][80];
    __shared__ float s_attn[NHEADS*64];
    __shared__ float s_proj[C*C];

    for (int i = t; i < 640; i += 512) {
        const int h = i / 80, idx = i - h*80;
        float v = 0.f;
        const float* p = g_part + ((b*NHEADS + h)*NTILE)*80 + idx;
        #pragma unroll 8
        for (int ch = 0; ch < NTILE; ch++) v += p[ch*80];
        red[h][idx] = v;
    }
    for (int i = t; i < C*C; i += 512) s_proj[i] = proj_w[i];
    __syncthreads();

    if (t < 128) {
        const int h = t >> 4, i = t & 15;
        red[h][64 + i] = fmaxf(sqrtf(red[h][64 + i]), 1e-12f);
    }
    __syncthreads();

    {
        const int h = t >> 6, i = t & 63;
        const int c2 = i >> 3, d = i & 7;
        const float logit = red[h][c2*8 + d] / (red[h][64 + c2] * red[h][72 + d]) * temp[h];
        float m = logit;
        #pragma unroll
        for (int o = 4; o > 0; o >>= 1) m = fmaxf(m, __shfl_xor_sync(0xffffffffu, m, o, 8));
        const float e = expf(logit - m);
        float s = e;
        #pragma unroll
        for (int o = 4; o > 0; o >>= 1) s += __shfl_xor_sync(0xffffffffu, s, o, 8);
        s_attn[h*64 + i] = e / s;
    }
    __syncthreads();

    for (int it = t; it < C*C; it += 512) {
        const int co = it >> 6, cv = it & 63, hh = cv >> 3, d = cv & 7;
        float acc = 0.f;
        #pragma unroll
        for (int cp = 0; cp < 8; cp++)
            acc += s_proj[co*64 + hh*8 + cp] * s_attn[hh*64 + cp*8 + d];
        g_weff[b*C*C + it] = acc;
    }
}

// ---------------- launcher ----------------
extern "C" void kernel_launch(void* const* d_in, const int* in_sizes, int n_in,
                              void* d_out, int out_size)
{
    const float* input1      = (const float*)d_in[0];
    const float* input2      = (const float*)d_in[1];
    const float* q_w         = (const float*)d_in[2];
    const float* q_dw_w      = (const float*)d_in[3];
    const float* kv_w        = (const float*)d_in[4];
    const float* kv_dw_w     = (const float*)d_in[5];
    const float* proj_w      = (const float*)d_in[6];
    const float* temperature = (const float*)d_in[7];
    float* out = (float*)d_out;

    uint16_t* midQ; cudaGetSymbolAddress((void**)&midQ, g_midQ16);
    uint16_t* midK; cudaGetSymbolAddress((void**)&midK, g_midK16);
    float* midV; cudaGetSymbolAddress((void**)&midV, g_midV);
    float* V;    cudaGetSymbolAddress((void**)&V,    g_V);
    float* Weff; cudaGetSymbolAddress((void**)&Weff, g_weff);

    dim3 ggemm(NPIX/128, BATCH);                 // (512, 4)
    dim3 gdw(1, HH/16, BATCH*C);
    dim3 gattn(NTILE, NHEADS, BATCH);

    gemm_bf16<true><<<ggemm, 128>>>(input1, q_w, midQ, 0);        // 1
    gemm_bf16_kv<<<ggemm, 256>>>(input2, kv_w, midK, midV);       // 2
    dw3x3<<<gdw, 256>>>(midV, kv_dw_w + C*9, V);                  // 3
    dwqk_attn<<<gattn, 512>>>(q_dw_w, kv_dw_w);                   // 4
    attn_tail<<<BATCH, 512>>>(temperature, proj_w);               // 5
    gemm_bf16<false><<<ggemm, 128>>>(V, Weff, out, 1);            // 6
}

// round 16
// speedup vs baseline: 1.0618x; 1.0618x over previous
#include <cuda_runtime.h>
#include <math.h>
#include <stdint.h>

#define BATCH 4
#define C 64
#define HH 256
#define WW 256
#define NPIX (HH*WW)
#define NHEADS 8
#define NTILE 64              // row tiles (4 rows each)
#define PITCHU 136            // uint32 smem pitch in gemm kernels
#define PAD 1028              // smem floats per channel row-block (16B-aligned)

// ---------------- scratch (static device globals) ----------------
__device__ float g_midQ[BATCH*C*NPIX];
__device__ float g_midK[BATCH*C*NPIX];
__device__ float g_midV[BATCH*C*NPIX];
__device__ float g_V[BATCH*C*NPIX];
__device__ float g_part[BATCH*NHEADS*NTILE*80];
__device__ float g_weff[BATCH*C*C];

// ---------------- bf16 3-split helpers ----------------
__device__ __forceinline__ uint32_t rbf16(float x){
    uint32_t b = __float_as_uint(x);
    return (b + 0x7FFFu + ((b >> 16) & 1u)) >> 16;
}
__device__ __forceinline__ void split2(float x0, float x1, uint32_t& hi, uint32_t& lo){
    const uint32_t h0 = rbf16(x0), h1 = rbf16(x1);
    hi = h0 | (h1 << 16);
    const float r0 = x0 - __uint_as_float(h0 << 16);
    const float r1 = x1 - __uint_as_float(h1 << 16);
    asm("cvt.rn.bf16x2.f32 %0, %1, %2;" : "=r"(lo) : "f"(r1), "f"(r0));
}

#define MMA_BF16(c0,c1,c2,c3,a0,a1,a2,a3,b0,b1) \
  asm volatile("mma.sync.aligned.m16n8k16.row.col.f32.bf16.bf16.f32 " \
    "{%0,%1,%2,%3}, {%4,%5,%6,%7}, {%8,%9}, {%0,%1,%2,%3};" \
    : "+f"(c0),"+f"(c1),"+f"(c2),"+f"(c3) \
    : "r"(a0),"r"(a1),"r"(a2),"r"(a3),"r"(b0),"r"(b1))

// ============ gemm_bf16: 64 out ch; 3 accumulator sets (chain = 4) ============
__global__ void __launch_bounds__(128) gemm_bf16(
    const float* __restrict__ in, const float* __restrict__ w,
    float* __restrict__ out, int w_per_batch)
{
    __shared__ uint32_t s_hi[32*PITCHU];
    __shared__ uint32_t s_lo[32*PITCHU];

    const int tid  = threadIdx.x;
    const int lane = tid & 31, warp = tid >> 5;
    const int b    = blockIdx.y;
    const int px0  = blockIdx.x * 128;
    const int gid  = lane >> 2, tig = lane & 3;

    const float* wb = w + (w_per_batch ? b*C*C : 0);
    uint32_t Wh[4][4], Wl[4][4];
    #pragma unroll
    for (int kc = 0; kc < 4; kc++) {
        #pragma unroll
        for (int j = 0; j < 4; j++) {
            const int row = warp*16 + gid + (j & 1)*8;
            const int p   = 8*kc + tig + (j >> 1)*4;
            const float2 x = *(const float2*)(wb + row*C + 2*p);
            split2(x.x, x.y, Wh[kc][j], Wl[kc][j]);
        }
    }

    const float* ib = in + (size_t)b*(C*NPIX) + px0;
    #pragma unroll
    for (int i = 0; i < 8; i++) {
        const int p = warp + 4*i;
        const float4 e = *(const float4*)(ib + (size_t)(2*p  )*NPIX + lane*4);
        const float4 o = *(const float4*)(ib + (size_t)(2*p+1)*NPIX + lane*4);
        uint32_t h0,l0,h1,l1,h2,l2,h3,l3;
        split2(e.x, o.x, h0, l0); split2(e.y, o.y, h1, l1);
        split2(e.z, o.z, h2, l2); split2(e.w, o.w, h3, l3);
        *(uint4*)(s_hi + p*PITCHU + lane*4) = make_uint4(h0,h1,h2,h3);
        *(uint4*)(s_lo + p*PITCHU + lane*4) = make_uint4(l0,l1,l2,l3);
    }
    __syncthreads();

    float* ob = out + (size_t)b*(C*NPIX) + px0;
    const int co_base = warp*16;
    #pragma unroll 2
    for (int nt = 0; nt < 16; nt++) {
        float A0=0.f,A1=0.f,A2=0.f,A3=0.f;
        float B0=0.f,B1=0.f,B2=0.f,B3=0.f;
        float D0=0.f,D1=0.f,D2=0.f,D3=0.f;
        const int pxl = nt*8 + gid;
        #pragma unroll
        for (int kc = 0; kc < 4; kc++) {
            const int r0 = (8*kc + tig)*PITCHU + pxl;
            const int r1 = r0 + 4*PITCHU;
            const uint32_t b0h = s_hi[r0], b1h = s_hi[r1];
            const uint32_t b0l = s_lo[r0], b1l = s_lo[r1];
            MMA_BF16(A0,A1,A2,A3, Wh[kc][0],Wh[kc][1],Wh[kc][2],Wh[kc][3], b0h,b1h);
            MMA_BF16(B0,B1,B2,B3, Wh[kc][0],Wh[kc][1],Wh[kc][2],Wh[kc][3], b0l,b1l);
            MMA_BF16(D0,D1,D2,D3, Wl[kc][0],Wl[kc][1],Wl[kc][2],Wl[kc][3], b0h,b1h);
        }
        const float c0 = A0 + B0 + D0, c1 = A1 + B1 + D1;
        const float c2 = A2 + B2 + D2, c3 = A3 + B3 + D3;
        const int pxs = nt*8 + tig*2;
        *(float2*)(ob + (size_t)(co_base+gid  )*NPIX + pxs) = make_float2(c0, c1);
        *(float2*)(ob + (size_t)(co_base+gid+8)*NPIX + pxs) = make_float2(c2, c3);
    }
}

// ======== gemm_bf16_kv: 128 out ch; 2 accumulator sets (chains 4/8) ===========
__global__ void __launch_bounds__(256) gemm_bf16_kv(
    const float* __restrict__ in, const float* __restrict__ w,
    float* __restrict__ outK, float* __restrict__ outV)
{
    __shared__ uint32_t s_hi[32*PITCHU];
    __shared__ uint32_t s_lo[32*PITCHU];

    const int tid  = threadIdx.x;
    const int lane = tid & 31, warp = tid >> 5;
    const int b    = blockIdx.y;
    const int px0  = blockIdx.x * 128;
    const int gid  = lane >> 2, tig = lane & 3;

    uint32_t Wh[4][4], Wl[4][4];
    #pragma unroll
    for (int kc = 0; kc < 4; kc++) {
        #pragma unroll
        for (int j = 0; j < 4; j++) {
            const int row = warp*16 + gid + (j & 1)*8;
            const int p   = 8*kc + tig + (j >> 1)*4;
            const float2 x = *(const float2*)(w + row*C + 2*p);
            split2(x.x, x.y, Wh[kc][j], Wl[kc][j]);
        }
    }

    const float* ib = in + (size_t)b*(C*NPIX) + px0;
    #pragma unroll
    for (int i = 0; i < 4; i++) {
        const int p = warp + 8*i;
        const float4 e = *(const float4*)(ib + (size_t)(2*p  )*NPIX + lane*4);
        const float4 o = *(const float4*)(ib + (size_t)(2*p+1)*NPIX + lane*4);
        uint32_t h0,l0,h1,l1,h2,l2,h3,l3;
        split2(e.x, o.x, h0, l0); split2(e.y, o.y, h1, l1);
        split2(e.z, o.z, h2, l2); split2(e.w, o.w, h3, l3);
        *(uint4*)(s_hi + p*PITCHU + lane*4) = make_uint4(h0,h1,h2,h3);
        *(uint4*)(s_lo + p*PITCHU + lane*4) = make_uint4(l0,l1,l2,l3);
    }
    __syncthreads();

    const int co_base = warp*16;
    float* ob = ((co_base < 64) ? outK : outV) + (size_t)b*(C*NPIX) + px0;
    const int co_loc = co_base & 63;
    #pragma unroll 2
    for (int nt = 0; nt < 16; nt++) {
        float A0=0.f,A1=0.f,A2=0.f,A3=0.f;
        float B0=0.f,B1=0.f,B2=0.f,B3=0.f;
        const int pxl = nt*8 + gid;
        #pragma unroll
        for (int kc = 0; kc < 4; kc++) {
            const int r0 = (8*kc + tig)*PITCHU + pxl;
            const int r1 = r0 + 4*PITCHU;
            const uint32_t b0h = s_hi[r0], b1h = s_hi[r1];
            const uint32_t b0l = s_lo[r0], b1l = s_lo[r1];
            MMA_BF16(A0,A1,A2,A3, Wh[kc][0],Wh[kc][1],Wh[kc][2],Wh[kc][3], b0h,b1h);
            MMA_BF16(B0,B1,B2,B3, Wh[kc][0],Wh[kc][1],Wh[kc][2],Wh[kc][3], b0l,b1l);
            MMA_BF16(B0,B1,B2,B3, Wl[kc][0],Wl[kc][1],Wl[kc][2],Wl[kc][3], b0h,b1h);
        }
        const float c0 = A0 + B0, c1 = A1 + B1, c2 = A2 + B2, c3 = A3 + B3;
        const int pxs = nt*8 + tig*2;
        *(float2*)(ob + (size_t)(co_loc+gid  )*NPIX + pxs) = make_float2(c0, c1);
        *(float2*)(ob + (size_t)(co_loc+gid+8)*NPIX + pxs) = make_float2(c2, c3);
    }
}

// ---------------- sliding-window row fetch ----------------
__device__ __forceinline__ void fetch_row(
    const float* __restrict__ ic, int yy, int x4, float4& m, float& l, float& r)
{
    if (yy < 0 || yy >= HH) { m = make_float4(0.f,0.f,0.f,0.f); l = 0.f; r = 0.f; return; }
    const float* row = ic + yy*WW;
    m = *(const float4*)(row + x4);
    l = (x4 > 0)      ? __ldg(row + x4 - 1) : 0.f;
    r = (x4 + 4 < WW) ? __ldg(row + x4 + 4) : 0.f;
}
__device__ __forceinline__ float4 stencil3(
    const float4& m0, float l0, float r0, const float4& m1, float l1, float r1,
    const float4& m2, float l2, float r2, const float* wr)
{
    float a0, a1, a2, a3;
    a0  = wr[0]*l0   + wr[1]*m0.x + wr[2]*m0.y;
    a1  = wr[0]*m0.x + wr[1]*m0.y + wr[2]*m0.z;
    a2  = wr[0]*m0.y + wr[1]*m0.z + wr[2]*m0.w;
    a3  = wr[0]*m0.z + wr[1]*m0.w + wr[2]*r0;
    a0 += wr[3]*l1   + wr[4]*m1.x + wr[5]*m1.y;
    a1 += wr[3]*m1.x + wr[4]*m1.y + wr[5]*m1.z;
    a2 += wr[3]*m1.y + wr[4]*m1.z + wr[5]*m1.w;
    a3 += wr[3]*m1.z + wr[4]*m1.w + wr[5]*r1;
    a0 += wr[6]*l2   + wr[7]*m2.x + wr[8]*m2.y;
    a1 += wr[6]*m2.x + wr[7]*m2.y + wr[8]*m2.z;
    a2 += wr[6]*m2.y + wr[7]*m2.z + wr[8]*m2.w;
    a3 += wr[6]*m2.z + wr[7]*m2.w + wr[8]*r2;
    return make_float4(a0, a1, a2, a3);
}
__device__ __forceinline__ float dot4(const float4& a, const float4& b){
    return a.x*b.x + a.y*b.y + a.z*b.z + a.w*b.w;
}

// ============ dwqk_attn: 512 threads, sliding-window phase 1, vec phase 2 =====
__global__ void __launch_bounds__(512, 2) dwqk_attn(
    const float* __restrict__ q_dw_w, const float* __restrict__ k_dw_w)
{
    __shared__ float s_q[8*PAD];
    __shared__ float s_k[8*PAD];
    __shared__ float s_red[80*16];

    const int tid  = threadIdx.x;
    const int tile = blockIdx.x;
    const int h    = blockIdx.y;
    const int b    = blockIdx.z;
    const int y0   = tile*4;

    const int lane = tid & 31, wrp = tid >> 5;

    // ---- phase 1: sliding-window depthwise ----
    {
        const int grp = tid >> 8;              // 0: q, 1: k
        const int t   = tid & 255;
        const int cg  = t & 63, cp = t >> 6;   // x group, channel pair
        const int x4  = cg*4;

        const float* src = (grp ? g_midK : g_midQ) + (size_t)b*(C*NPIX);
        const float* dwb = (grp ? k_dw_w : q_dw_w) + h*8*9;
        float* dst       = grp ? s_k : s_q;

        #pragma unroll
        for (int jj = 0; jj < 2; jj++) {
            const int j = cp*2 + jj;
            const float* ic = src + (size_t)(h*8 + j)*NPIX;
            float wr[9];
            #pragma unroll
            for (int i = 0; i < 9; i++) wr[i] = __ldg(dwb + j*9 + i);

            float4 m0, m1, m2; float l0, l1, l2, r0, r1, r2;
            fetch_row(ic, y0 - 1, x4, m0, l0, r0);
            fetch_row(ic, y0,     x4, m1, l1, r1);
            #pragma unroll
            for (int rowl = 0; rowl < 4; rowl++) {
                fetch_row(ic, y0 + rowl + 1, x4, m2, l2, r2);
                const float4 res = stencil3(m0, l0, r0, m1, l1, r1, m2, l2, r2, wr);
                *(float4*)(dst + j*PAD + rowl*256 + x4) = res;
                m0 = m1; l0 = l1; r0 = r1;
                m1 = m2; l1 = l2; r1 = r2;
            }
        }
    }
    __syncthreads();

    // ---- phase 2: quad split, float4 pixel groups ----
    const int quad = tid & 3, slot = tid >> 2;
    float S[16], qs[2], ks[8];
    #pragma unroll
    for (int i = 0; i < 16; i++) S[i] = 0.f;
    qs[0] = qs[1] = 0.f;
    #pragma unroll
    for (int i = 0; i < 8; i++) ks[i] = 0.f;

    const float* qp = s_q + quad*2*PAD;
    #pragma unroll
    for (int it = 0; it < 2; it++) {
        const int n4 = it*512 + slot*4;
        const float4 q0 = *(const float4*)(qp + n4);
        const float4 q1 = *(const float4*)(qp + PAD + n4);
        qs[0] += dot4(q0, q0);
        qs[1] += dot4(q1, q1);
        #pragma unroll
        for (int jb = 0; jb < 2; jb++) {
            float4 kv[4];
            #pragma unroll
            for (int jj = 0; jj < 4; jj++)
                kv[jj] = *(const float4*)(s_k + (jb*4 + jj)*PAD + n4);
            #pragma unroll
            for (int jj = 0; jj < 4; jj++) {
                const int d = jb*4 + jj;
                S[d]     += dot4(q0, kv[jj]);
                S[8 + d] += dot4(q1, kv[jj]);
                ks[d]    += dot4(kv[jj], kv[jj]);
            }
        }
    }

    #pragma unroll
    for (int i = 0; i < 16; i++) {
        float v = S[i];
        #pragma unroll
        for (int o = 4; o <= 16; o <<= 1) v += __shfl_xor_sync(0xffffffffu, v, o);
        if (lane < 4) s_red[(i + 16*lane)*16 + wrp] = v;
    }
    #pragma unroll
    for (int i = 0; i < 2; i++) {
        float v = qs[i];
        #pragma unroll
        for (int o = 4; o <= 16; o <<= 1) v += __shfl_xor_sync(0xffffffffu, v, o);
        if (lane < 4) s_red[(64 + 2*lane + i)*16 + wrp] = v;
    }
    #pragma unroll
    for (int i = 0; i < 8; i++) {
        float v = ks[i];
        #pragma unroll
        for (int o = 1; o <= 16; o <<= 1) v += __shfl_xor_sync(0xffffffffu, v, o);
        if (lane == 0) s_red[(72 + i)*16 + wrp] = 0.25f*v;
    }
    __syncthreads();
    if (tid < 80) {
        float v = 0.f;
        #pragma unroll
        for (int w = 0; w < 16; w++) v += s_red[tid*16 + w];
        g_part[((b*NHEADS + h)*NTILE + tile)*80 + tid] = v;
    }
}

// ---------------- depthwise 3x3 (V path), sliding window ----------------------
__global__ void __launch_bounds__(256) dw3x3(
    const float* __restrict__ in, const float* __restrict__ w,
    float* __restrict__ out)
{
    const int z = blockIdx.z;
    const float* ib = in + (size_t)z*NPIX;
    float* ob = out + (size_t)z*NPIX;
    const float* wc = w + (z & (C-1))*9;

    const int tid = threadIdx.x;
    const int x4  = (tid & 63)*4;
    const int y0  = blockIdx.y*16 + (tid >> 6)*4;

    float wr[9];
    #pragma unroll
    for (int i = 0; i < 9; i++) wr[i] = __ldg(wc + i);

    float4 m0, m1, m2; float l0, l1, l2, r0, r1, r2;
    fetch_row(ib, y0 - 1, x4, m0, l0, r0);
    fetch_row(ib, y0,     x4, m1, l1, r1);
    #pragma unroll
    for (int rowl = 0; rowl < 4; rowl++) {
        fetch_row(ib, y0 + rowl + 1, x4, m2, l2, r2);
        const float4 res = stencil3(m0, l0, r0, m1, l1, r1, m2, l2, r2, wr);
        *(float4*)(ob + (y0 + rowl)*WW + x4) = res;
        m0 = m1; l0 = l1; r0 = r1;
        m1 = m2; l1 = l2; r1 = r2;
    }
}

// ===== attn_tail: reduce partials + norms + softmax + weff in ONE launch ======
__global__ void __launch_bounds__(512) attn_tail(
    const float* __restrict__ temp, const float* __restrict__ proj_w)
{
    const int b = blockIdx.x;
    const int t = threadIdx.x;
    __shared__ float red[NHEADS][80];
    __shared__ float s_attn[NHEADS*64];
    __shared__ float s_proj[C*C];

    for (int i = t; i < 640; i += 512) {
        const int h = i / 80, idx = i - h*80;
        float v = 0.f;
        const float* p = g_part + ((b*NHEADS + h)*NTILE)*80 + idx;
        #pragma unroll 8
        for (int ch = 0; ch < NTILE; ch++) v += p[ch*80];
        red[h][idx] = v;
    }
    for (int i = t; i < C*C; i += 512) s_proj[i] = proj_w[i];
    __syncthreads();

    if (t < 128) {
        const int h = t >> 4, i = t & 15;
        red[h][64 + i] = fmaxf(sqrtf(red[h][64 + i]), 1e-12f);
    }
    __syncthreads();

    {
        const int h = t >> 6, i = t & 63;
        const int c2 = i >> 3, d = i & 7;
        const float logit = red[h][c2*8 + d] / (red[h][64 + c2] * red[h][72 + d]) * temp[h];
        float m = logit;
        #pragma unroll
        for (int o = 4; o > 0; o >>= 1) m = fmaxf(m, __shfl_xor_sync(0xffffffffu, m, o, 8));
        const float e = expf(logit - m);
        float s = e;
        #pragma unroll
        for (int o = 4; o > 0; o >>= 1) s += __shfl_xor_sync(0xffffffffu, s, o, 8);
        s_attn[h*64 + i] = e / s;
    }
    __syncthreads();

    for (int it = t; it < C*C; it += 512) {
        const int co = it >> 6, cv = it & 63, hh = cv >> 3, d = cv & 7;
        float acc = 0.f;
        #pragma unroll
        for (int cp = 0; cp < 8; cp++)
            acc += s_proj[co*64 + hh*8 + cp] * s_attn[hh*64 + cp*8 + d];
        g_weff[b*C*C + it] = acc;
    }
}

// ---------------- launcher: two-stream fork/join (graph-capturable) -----------
extern "C" void kernel_launch(void* const* d_in, const int* in_sizes, int n_in,
                              void* d_out, int out_size)
{
    const float* input1      = (const float*)d_in[0];
    const float* input2      = (const float*)d_in[1];
    const float* q_w         = (const float*)d_in[2];
    const float* q_dw_w      = (const float*)d_in[3];
    const float* kv_w        = (const float*)d_in[4];
    const float* kv_dw_w     = (const float*)d_in[5];
    const float* proj_w      = (const float*)d_in[6];
    const float* temperature = (const float*)d_in[7];
    float* out = (float*)d_out;

    float* midQ; cudaGetSymbolAddress((void**)&midQ, g_midQ);
    float* midK; cudaGetSymbolAddress((void**)&midK, g_midK);
    float* midV; cudaGetSymbolAddress((void**)&midV, g_midV);
    float* V;    cudaGetSymbolAddress((void**)&V,    g_V);
    float* Weff; cudaGetSymbolAddress((void**)&Weff, g_weff);

    // one-time side-stream + event setup (host objects only; no device memory)
    static cudaStream_t s2 = nullptr;
    static cudaEvent_t eFork = nullptr, eQ = nullptr, eKV = nullptr, eDW = nullptr;
    if (!s2) {
        cudaStreamCreateWithFlags(&s2, cudaStreamNonBlocking);
        cudaEventCreateWithFlags(&eFork, cudaEventDisableTiming);
        cudaEventCreateWithFlags(&eQ,    cudaEventDisableTiming);
        cudaEventCreateWithFlags(&eKV,   cudaEventDisableTiming);
        cudaEventCreateWithFlags(&eDW,   cudaEventDisableTiming);
    }

    dim3 ggemm(NPIX/128, BATCH);                 // (512, 4)
    dim3 gdw(1, HH/16, BATCH*C);
    dim3 gattn(NTILE, NHEADS, BATCH);

    // fork side stream from main (captured) stream
    cudaEventRecord(eFork, 0);
    cudaStreamWaitEvent(s2, eFork, 0);

    // s2: gemm_q (input1 path)  ||  main: gemm_kv (input2 path)
    gemm_bf16<<<ggemm, 128, 0, s2>>>(input1, q_w, midQ, 0);
    cudaEventRecord(eQ, s2);

    gemm_bf16_kv<<<ggemm, 256>>>(input2, kv_w, midK, midV);
    cudaEventRecord(eKV, 0);

    // s2: dw3x3 (needs midV)  ||  main: dwqk (needs midQ+midK)
    cudaStreamWaitEvent(s2, eKV, 0);
    dw3x3<<<gdw, 256, 0, s2>>>(midV, kv_dw_w + C*9, V);
    cudaEventRecord(eDW, s2);

    cudaStreamWaitEvent(0, eQ, 0);
    dwqk_attn<<<gattn, 512>>>(q_dw_w, kv_dw_w);
    attn_tail<<<BATCH, 512>>>(temperature, proj_w);

    // main: final gemm needs V (s2) + Weff (main)
    cudaStreamWaitEvent(0, eDW, 0);
    gemm_bf16<<<ggemm, 128>>>(V, Weff, out, 1);
}